// round 3
// baseline (speedup 1.0000x reference)
#include <cuda_runtime.h>
#include <cuda_bf16.h>

// Problem constants (fixed by the reference):
//   B=128, S=2048, EMB=128, HID=256 (4H=1024), OUT=32, VOCAB=50257
// Only emb[:, S-1] (fwd) and emb[:, 0] (bwd) are used; f-gate is dead; Whf/Whb unused.

#define NB_B   128
#define NB_S   2048
#define NB_EMB 128
#define NB_HID 256
#define NB_OUT 32

// Intermediate hy[B][HID] lives in a device global (no allocations allowed).
__device__ float g_hy[NB_B * NB_HID];

__device__ __forceinline__ float sigm(float x) { return 1.0f / (1.0f + expf(-x)); }

// ---------------------------------------------------------------------------
// Kernel 1: compute hy = hy_f + hy_b for all (batch, h).
// Grid: 128 blocks = 32 h-chunks (8 h each) x 4 batch-groups (32 batches each).
// Block: 256 threads; warp = one h, lanes = 32 batches (broadcast W LDGs).
// Shared x rows padded to 132 floats -> conflict-free LDS.128 across lanes.
// ---------------------------------------------------------------------------
__global__ void __launch_bounds__(256, 1) lstm_hy_kernel(
    const int*   __restrict__ inputs,   // [B, S] int32
    const float* __restrict__ weight,   // [VOCAB, EMB]
    const float* __restrict__ Wxf,      // [1024, 128]
    const float* __restrict__ bxf,      // [1024]
    const float* __restrict__ bhf,      // [1024]
    const float* __restrict__ Wxb,      // [1024, 128]
    const float* __restrict__ bxb,      // [1024]
    const float* __restrict__ bhb)      // [1024]
{
    // xs[dir][lb][e], e-stride padded 128 -> 132
    __shared__ float xs[2 * 32 * 132];
    __shared__ int   tok_s[64];         // [dir][lb]

    const int tid    = threadIdx.x;
    const int hc     = blockIdx.x & 31;     // h-chunk 0..31
    const int bg     = blockIdx.x >> 5;     // batch-group 0..3
    const int h_base = hc * 8;
    const int b_base = bg * 32;

    // Stage tokens once: dir 0 = forward (t = S-1), dir 1 = backward (t = 0)
    if (tid < 64) {
        const int dir = tid >> 5;
        const int lb  = tid & 31;
        tok_s[tid] = inputs[(b_base + lb) * NB_S + (dir ? 0 : (NB_S - 1))];
    }
    __syncthreads();

    // Gather embeddings into padded shared rows (coalesced along e).
    for (int idx = tid; idx < 2 * 32 * NB_EMB; idx += 256) {
        const int dir = idx >> 12;          // /4096
        const int lb  = (idx >> 7) & 31;
        const int e   = idx & 127;
        const int tok = tok_s[dir * 32 + lb];
        xs[dir * 4224 + lb * 132 + e] = weight[tok * NB_EMB + e];
    }
    __syncthreads();

    const int hl = tid >> 5;                // warp id = local h
    const int lb = tid & 31;                // lane    = local batch
    const int h  = h_base + hl;
    const int b  = b_base + lb;

    const float4* xf = (const float4*)(xs + lb * 132);           // 528B stride, 16B aligned
    const float4* xb = (const float4*)(xs + 4224 + lb * 132);

    // Gate rows: i at h, g at 512+h, o at 768+h (f-gate skipped: c=0)
    const float4* wif = (const float4*)(Wxf + (h)       * NB_EMB);
    const float4* wgf = (const float4*)(Wxf + (512 + h) * NB_EMB);
    const float4* wof = (const float4*)(Wxf + (768 + h) * NB_EMB);
    const float4* wib = (const float4*)(Wxb + (h)       * NB_EMB);
    const float4* wgb = (const float4*)(Wxb + (512 + h) * NB_EMB);
    const float4* wob = (const float4*)(Wxb + (768 + h) * NB_EMB);

    float aif = 0.f, agf = 0.f, aof = 0.f;
    float aib = 0.f, agb = 0.f, aob = 0.f;

    #pragma unroll 8
    for (int k = 0; k < NB_EMB / 4; k++) {
        const float4 a = xf[k];
        const float4 c = xb[k];
        float4 w;
        w = wif[k];
        aif = fmaf(w.x, a.x, fmaf(w.y, a.y, fmaf(w.z, a.z, fmaf(w.w, a.w, aif))));
        w = wgf[k];
        agf = fmaf(w.x, a.x, fmaf(w.y, a.y, fmaf(w.z, a.z, fmaf(w.w, a.w, agf))));
        w = wof[k];
        aof = fmaf(w.x, a.x, fmaf(w.y, a.y, fmaf(w.z, a.z, fmaf(w.w, a.w, aof))));
        w = wib[k];
        aib = fmaf(w.x, c.x, fmaf(w.y, c.y, fmaf(w.z, c.z, fmaf(w.w, c.w, aib))));
        w = wgb[k];
        agb = fmaf(w.x, c.x, fmaf(w.y, c.y, fmaf(w.z, c.z, fmaf(w.w, c.w, agb))));
        w = wob[k];
        aob = fmaf(w.x, c.x, fmaf(w.y, c.y, fmaf(w.z, c.z, fmaf(w.w, c.w, aob))));
    }

    // Biases: gates = x@Wx.T + bx + bh  (h2h(0) contributes only bh)
    const float gif = aif + bxf[h]       + bhf[h];
    const float ggf = agf + bxf[512 + h] + bhf[512 + h];
    const float gof = aof + bxf[768 + h] + bhf[768 + h];
    const float gib = aib + bxb[h]       + bhb[h];
    const float ggb = agb + bxb[512 + h] + bhb[512 + h];
    const float gob = aob + bxb[768 + h] + bhb[768 + h];

    const float cyf = sigm(gif) * tanhf(ggf);
    const float hyf = sigm(gof) * tanhf(cyf);
    const float cyb = sigm(gib) * tanhf(ggb);
    const float hyb = sigm(gob) * tanhf(cyb);

    g_hy[b * NB_HID + h] = hyf + hyb;
}

// ---------------------------------------------------------------------------
// Kernel 2: logits = hy @ Why.T + by ; out = log_softmax(logits).
// One warp per batch; lane = one of the 32 outputs; butterfly max/sum.
// ---------------------------------------------------------------------------
__global__ void __launch_bounds__(32, 1) head_kernel(
    const float* __restrict__ Why,   // [32, 256]
    const float* __restrict__ by,    // [32]
    float*       __restrict__ out)   // [B, 32]
{
    __shared__ float hy_s[NB_HID];
    const int b = blockIdx.x;
    const int o = threadIdx.x;

    #pragma unroll
    for (int i = o; i < NB_HID; i += 32)
        hy_s[i] = g_hy[b * NB_HID + i];
    __syncwarp();

    const float4* w4 = (const float4*)(Why + o * NB_HID);
    const float4* h4 = (const float4*)hy_s;

    float acc = by[o];
    #pragma unroll 8
    for (int k = 0; k < NB_HID / 4; k++) {
        const float4 w = w4[k];
        const float4 h = h4[k];
        acc = fmaf(w.x, h.x, fmaf(w.y, h.y, fmaf(w.z, h.z, fmaf(w.w, h.w, acc))));
    }

    // log_softmax over the 32 lanes
    float mx = acc;
    #pragma unroll
    for (int off = 16; off; off >>= 1)
        mx = fmaxf(mx, __shfl_xor_sync(0xffffffffu, mx, off));
    float s = expf(acc - mx);
    #pragma unroll
    for (int off = 16; off; off >>= 1)
        s += __shfl_xor_sync(0xffffffffu, s, off);

    out[b * NB_OUT + o] = acc - mx - logf(s);
}

// ---------------------------------------------------------------------------
// Launch. Inputs in metadata order:
// 0 inputs(int32) 1 weight 2 Wxf 3 bxf 4 Whf(unused) 5 bhf
// 6 Wxb 7 bxb 8 Whb(unused) 9 bhb 10 Why 11 by
// ---------------------------------------------------------------------------
extern "C" void kernel_launch(void* const* d_in, const int* in_sizes, int n_in,
                              void* d_out, int out_size)
{
    const int*   inputs = (const int*)  d_in[0];
    const float* weight = (const float*)d_in[1];
    const float* Wxf    = (const float*)d_in[2];
    const float* bxf    = (const float*)d_in[3];
    const float* bhf    = (const float*)d_in[5];
    const float* Wxb    = (const float*)d_in[6];
    const float* bxb    = (const float*)d_in[7];
    const float* bhb    = (const float*)d_in[9];
    const float* Why    = (const float*)d_in[10];
    const float* by     = (const float*)d_in[11];
    float*       out    = (float*)d_out;

    lstm_hy_kernel<<<128, 256>>>(inputs, weight, Wxf, bxf, bhf, Wxb, bxb, bhb);
    head_kernel<<<128, 32>>>(Why, by, out);
}